// round 1
// baseline (speedup 1.0000x reference)
#include <cuda_runtime.h>

#define EPS_VAL 1e-11f

// Scratch (allocation-free rule: __device__ globals)
__device__ float g_q [4*16*2048*64];   // [B,H,S,dk]
__device__ float g_k [4*16*2048*64];
__device__ float g_v [4*16*2048*64];
__device__ float g_ao[4*2048*1024];    // [B,S,H*dk] attention output

// ---------------------------------------------------------------------------
// C = A[8192,1024] @ W[1024,1024]^T + bias
// mode 0: scatter output column j=(h*64+d) into [B,H,S,dk] layout (QKV proj)
// mode 1: plain row-major [8192,1024] (final projection -> d_out)
// Tiles: BM=BN=64, BK=16, 256 threads, 4x4 microtile, A/W transposed in smem
// (stride 68 => conflict-free float4 reads, 2-way-max stores).
// ---------------------------------------------------------------------------
__global__ __launch_bounds__(256) void gemm_nt(
    const float* __restrict__ A, const float* __restrict__ W,
    const float* __restrict__ bias, float* __restrict__ out, int mode)
{
    __shared__ float As[16][68];
    __shared__ float Ws[16][68];
    const int tid = threadIdx.x;
    const int tx = tid & 15, ty = tid >> 4;
    const int m0 = blockIdx.y << 6;
    const int n0 = blockIdx.x << 6;
    const int lr = tid >> 2;          // 0..63 tile row
    const int lc = (tid & 3) << 2;    // 0,4,8,12 k-offset

    const float* Ag = A + (size_t)(m0 + lr) * 1024 + lc;
    const float* Wg = W + (size_t)(n0 + lr) * 1024 + lc;

    float acc[4][4] = {};

    for (int kt = 0; kt < 1024; kt += 16) {
        float4 av = *reinterpret_cast<const float4*>(Ag + kt);
        float4 wv = *reinterpret_cast<const float4*>(Wg + kt);
        __syncthreads();
        As[lc+0][lr] = av.x; As[lc+1][lr] = av.y; As[lc+2][lr] = av.z; As[lc+3][lr] = av.w;
        Ws[lc+0][lr] = wv.x; Ws[lc+1][lr] = wv.y; Ws[lc+2][lr] = wv.z; Ws[lc+3][lr] = wv.w;
        __syncthreads();
        #pragma unroll
        for (int k = 0; k < 16; ++k) {
            float4 a4 = *reinterpret_cast<const float4*>(&As[k][ty << 2]);
            float4 w4 = *reinterpret_cast<const float4*>(&Ws[k][tx << 2]);
            float aa[4] = {a4.x, a4.y, a4.z, a4.w};
            float ww[4] = {w4.x, w4.y, w4.z, w4.w};
            #pragma unroll
            for (int i = 0; i < 4; ++i)
                #pragma unroll
                for (int j = 0; j < 4; ++j)
                    acc[i][j] = fmaf(aa[i], ww[j], acc[i][j]);
        }
    }

    float4 b4 = *reinterpret_cast<const float4*>(bias + n0 + (tx << 2));
    float bb[4] = {b4.x, b4.y, b4.z, b4.w};

    if (mode == 0) {
        const int col = n0 + (tx << 2);
        const int h = col >> 6, d = col & 63;
        #pragma unroll
        for (int i = 0; i < 4; ++i) {
            const int row = m0 + (ty << 2) + i;
            const int b = row >> 11, s = row & 2047;
            float4 r = make_float4(acc[i][0]+bb[0], acc[i][1]+bb[1],
                                   acc[i][2]+bb[2], acc[i][3]+bb[3]);
            *reinterpret_cast<float4*>(
                &out[((size_t)((b << 4) + h) * 2048 + s) * 64 + d]) = r;
        }
    } else {
        #pragma unroll
        for (int i = 0; i < 4; ++i) {
            const int row = m0 + (ty << 2) + i;
            float4 r = make_float4(acc[i][0]+bb[0], acc[i][1]+bb[1],
                                   acc[i][2]+bb[2], acc[i][3]+bb[3]);
            *reinterpret_cast<float4*>(&out[(size_t)row * 1024 + n0 + (tx << 2)]) = r;
        }
    }
}

// ---------------------------------------------------------------------------
// Flash attention, fp32, online softmax. One block = 64 q-rows of one (b,h).
// Grid: (S/64=32 q-tiles [x, fast], B*H=64 [y]) => K/V tiles of a head get
// L2 reuse across concurrently running q-tiles; mask shared across heads.
// Semantics match reference exactly: score = QK^T/8; masked -> EPS; softmax.
// ---------------------------------------------------------------------------
__global__ __launch_bounds__(256) void attn_kernel(const int* __restrict__ mask)
{
    extern __shared__ float sm[];
    float* Qts = sm;                 // [64 d][68]  (Q transposed)
    float* Kts = Qts + 64 * 68;      // [64 d][68]  (K transposed)
    float* Vsm = Kts + 64 * 68;      // [64 k][68]
    float* Psm = Vsm + 64 * 68;      // [64 q][68]  exp(scores)
    int*   Msm = reinterpret_cast<int*>(Psm + 64 * 68); // [64 q][68]

    const int tid = threadIdx.x;
    const int tx = tid & 15, ty = tid >> 4;
    const int bh = blockIdx.y;
    const int b = bh >> 4, h = bh & 15;
    const int q0 = blockIdx.x << 6;

    const float* Qg = g_q + (size_t)bh * 2048 * 64;
    const float* Kg = g_k + (size_t)bh * 2048 * 64;
    const float* Vg = g_v + (size_t)bh * 2048 * 64;
    const int*   Mg = mask + (size_t)b * 2048 * 2048;

    // Load Q tile once, transposed by d
    #pragma unroll
    for (int i = 0; i < 4; ++i) {
        int idx = tid + (i << 8);
        int r = idx >> 4, c = (idx & 15) << 2;
        float4 qv = *reinterpret_cast<const float4*>(Qg + (size_t)(q0 + r) * 64 + c);
        Qts[(c+0)*68 + r] = qv.x;
        Qts[(c+1)*68 + r] = qv.y;
        Qts[(c+2)*68 + r] = qv.z;
        Qts[(c+3)*68 + r] = qv.w;
    }

    float o[4][4] = {};
    float mrow[4] = {-1e30f, -1e30f, -1e30f, -1e30f};
    float lrow[4] = {};

    for (int k0 = 0; k0 < 2048; k0 += 64) {
        __syncthreads();  // prev PV done before overwriting K/V/M
        #pragma unroll
        for (int i = 0; i < 4; ++i) {
            int idx = tid + (i << 8);
            int r = idx >> 4, c = (idx & 15) << 2;
            float4 kv = *reinterpret_cast<const float4*>(Kg + (size_t)(k0 + r) * 64 + c);
            Kts[(c+0)*68 + r] = kv.x;
            Kts[(c+1)*68 + r] = kv.y;
            Kts[(c+2)*68 + r] = kv.z;
            Kts[(c+3)*68 + r] = kv.w;
            float4 vv = *reinterpret_cast<const float4*>(Vg + (size_t)(k0 + r) * 64 + c);
            *reinterpret_cast<float4*>(&Vsm[r*68 + c]) = vv;
            int4 mv = *reinterpret_cast<const int4*>(Mg + (size_t)(q0 + r) * 2048 + k0 + c);
            *reinterpret_cast<int4*>(&Msm[r*68 + c]) = mv;
        }
        __syncthreads();

        // S = Q K^T  (64x64x64)
        float sc[4][4] = {};
        #pragma unroll 8
        for (int d = 0; d < 64; ++d) {
            float4 q4 = *reinterpret_cast<const float4*>(&Qts[d*68 + (ty << 2)]);
            float4 k4 = *reinterpret_cast<const float4*>(&Kts[d*68 + (tx << 2)]);
            float qa[4] = {q4.x, q4.y, q4.z, q4.w};
            float ka[4] = {k4.x, k4.y, k4.z, k4.w};
            #pragma unroll
            for (int i = 0; i < 4; ++i)
                #pragma unroll
                for (int j = 0; j < 4; ++j)
                    sc[i][j] = fmaf(qa[i], ka[j], sc[i][j]);
        }

        // scale, mask, online softmax update (row stats replicated over 16 lanes)
        #pragma unroll
        for (int i = 0; i < 4; ++i) {
            const int qr = (ty << 2) + i;
            float p[4];
            #pragma unroll
            for (int j = 0; j < 4; ++j) {
                int mk = Msm[qr*68 + (tx << 2) + j];
                p[j] = (mk == 0) ? EPS_VAL : sc[i][j] * 0.125f;
            }
            float tm = fmaxf(fmaxf(p[0], p[1]), fmaxf(p[2], p[3]));
            #pragma unroll
            for (int off = 8; off > 0; off >>= 1)
                tm = fmaxf(tm, __shfl_xor_sync(0xffffffffu, tm, off));
            float mn = fmaxf(mrow[i], tm);
            float corr = __expf(mrow[i] - mn);
            float rs = 0.f;
            #pragma unroll
            for (int j = 0; j < 4; ++j) {
                float e = __expf(p[j] - mn);
                Psm[qr*68 + (tx << 2) + j] = e;
                rs += e;
            }
            #pragma unroll
            for (int off = 8; off > 0; off >>= 1)
                rs += __shfl_xor_sync(0xffffffffu, rs, off);
            lrow[i] = lrow[i] * corr + rs;
            mrow[i] = mn;
            #pragma unroll
            for (int j = 0; j < 4; ++j) o[i][j] *= corr;
        }
        __syncthreads();

        // O += P V   (64x64x64)
        #pragma unroll 4
        for (int k = 0; k < 64; k += 4) {
            float4 pv[4], vv[4];
            #pragma unroll
            for (int i = 0; i < 4; ++i)
                pv[i] = *reinterpret_cast<const float4*>(&Psm[((ty << 2) + i)*68 + k]);
            #pragma unroll
            for (int e = 0; e < 4; ++e)
                vv[e] = *reinterpret_cast<const float4*>(&Vsm[(k + e)*68 + (tx << 2)]);
            #pragma unroll
            for (int i = 0; i < 4; ++i) {
                float pa[4] = {pv[i].x, pv[i].y, pv[i].z, pv[i].w};
                #pragma unroll
                for (int e = 0; e < 4; ++e) {
                    o[i][0] = fmaf(pa[e], vv[e].x, o[i][0]);
                    o[i][1] = fmaf(pa[e], vv[e].y, o[i][1]);
                    o[i][2] = fmaf(pa[e], vv[e].z, o[i][2]);
                    o[i][3] = fmaf(pa[e], vv[e].w, o[i][3]);
                }
            }
        }
    }

    // normalize + write [B,S,H*dk]
    #pragma unroll
    for (int i = 0; i < 4; ++i) {
        float inv = 1.f / lrow[i];
        int q = q0 + (ty << 2) + i;
        float4 r = make_float4(o[i][0]*inv, o[i][1]*inv, o[i][2]*inv, o[i][3]*inv);
        *reinterpret_cast<float4*>(
            &g_ao[((size_t)(b * 2048 + q)) * 1024 + h * 64 + (tx << 2)]) = r;
    }
}

// ---------------------------------------------------------------------------
extern "C" void kernel_launch(void* const* d_in, const int* in_sizes, int n_in,
                              void* d_out, int out_size)
{
    const float* query = (const float*)d_in[0];
    const float* key_  = (const float*)d_in[1];
    const float* value = (const float*)d_in[2];
    const int*   mask  = (const int*)  d_in[3];
    const float* wq = (const float*)d_in[4];
    const float* bq = (const float*)d_in[5];
    const float* wk = (const float*)d_in[6];
    const float* bk = (const float*)d_in[7];
    const float* wv = (const float*)d_in[8];
    const float* bv = (const float*)d_in[9];
    const float* wo = (const float*)d_in[10];
    const float* bo = (const float*)d_in[11];

    float *pq, *pk, *pv, *pao;
    cudaGetSymbolAddress((void**)&pq,  g_q);
    cudaGetSymbolAddress((void**)&pk,  g_k);
    cudaGetSymbolAddress((void**)&pv,  g_v);
    cudaGetSymbolAddress((void**)&pao, g_ao);

    dim3 gg(16, 128);  // N/64, M/64
    gemm_nt<<<gg, 256>>>(query, wq, bq, pq, 0);
    gemm_nt<<<gg, 256>>>(key_,  wk, bk, pk, 0);
    gemm_nt<<<gg, 256>>>(value, wv, bv, pv, 0);

    const int smem = 5 * 64 * 68 * 4;  // 87040 B
    cudaFuncSetAttribute(attn_kernel,
                         cudaFuncAttributeMaxDynamicSharedMemorySize, smem);
    attn_kernel<<<dim3(32, 64), 256, smem>>>(mask);

    gemm_nt<<<gg, 256>>>(pao, wo, bo, (float*)d_out, 1);
}

// round 3
// speedup vs baseline: 1.4240x; 1.4240x over previous
#include <cuda_runtime.h>
#include <cuda_bf16.h>
#include <cstdint>

#define EPS_VAL 1e-11f

// ---------------- scratch (__device__ globals; no allocs allowed) -----------
__device__ float g_q [4*16*2048*64];   // [B,H,S,dk]
__device__ float g_k [4*16*2048*64];
__device__ float g_v [4*16*2048*64];
__device__ float g_ao[4*2048*1024];    // [B,S,H*dk]
__device__ __nv_bfloat16 g_ahi[8192*1024];
__device__ __nv_bfloat16 g_alo[8192*1024];
__device__ __nv_bfloat16 g_whi[1024*1024];
__device__ __nv_bfloat16 g_wlo[1024*1024];

// ---------------- PTX helpers (generic ISA, valid at compute_103) -----------
__device__ __forceinline__ uint32_t smem_u32(const void* p) {
    uint32_t a;
    asm("{ .reg .u64 t; cvta.to.shared.u64 t, %1; cvt.u32.u64 %0, t; }"
        : "=r"(a) : "l"(p));
    return a;
}
__device__ __forceinline__ void cpa16(uint32_t dst, const void* src) {
    asm volatile("cp.async.cg.shared.global [%0], [%1], 16;"
                 :: "r"(dst), "l"(src) : "memory");
}
#define CP_COMMIT() asm volatile("cp.async.commit_group;" ::: "memory")
#define CP_WAIT(n)  asm volatile("cp.async.wait_group %0;" :: "n"(n) : "memory")

#define LDSM4(r0, r1, r2, r3, addr)                                          \
    asm volatile("ldmatrix.sync.aligned.m8n8.x4.shared.b16 {%0,%1,%2,%3}, [%4];" \
                 : "=r"(r0), "=r"(r1), "=r"(r2), "=r"(r3) : "r"(addr))

#define MMA16816(d, a, b)                                                    \
    asm volatile("mma.sync.aligned.m16n8k16.row.col.f32.bf16.bf16.f32 "      \
                 "{%0,%1,%2,%3}, {%4,%5,%6,%7}, {%8,%9}, {%0,%1,%2,%3};"     \
                 : "+f"((d)[0]), "+f"((d)[1]), "+f"((d)[2]), "+f"((d)[3])    \
                 : "r"((a)[0]), "r"((a)[1]), "r"((a)[2]), "r"((a)[3]),       \
                   "r"((b)[0]), "r"((b)[1]))

// ---------------- fp32 -> bf16 hi/lo split ----------------------------------
__device__ __forceinline__ uint32_t pack_bf2(__nv_bfloat16 a, __nv_bfloat16 b) {
    return (uint32_t)__bfloat16_as_ushort(a) |
           ((uint32_t)__bfloat16_as_ushort(b) << 16);
}
__global__ __launch_bounds__(256) void conv_split(
    const float4* __restrict__ src, uint2* __restrict__ hi,
    uint2* __restrict__ lo, int n4)
{
    int i = blockIdx.x * blockDim.x + threadIdx.x;
    if (i >= n4) return;
    float4 v = src[i];
    __nv_bfloat16 h0 = __float2bfloat16(v.x), h1 = __float2bfloat16(v.y);
    __nv_bfloat16 h2 = __float2bfloat16(v.z), h3 = __float2bfloat16(v.w);
    __nv_bfloat16 l0 = __float2bfloat16(v.x - __bfloat162float(h0));
    __nv_bfloat16 l1 = __float2bfloat16(v.y - __bfloat162float(h1));
    __nv_bfloat16 l2 = __float2bfloat16(v.z - __bfloat162float(h2));
    __nv_bfloat16 l3 = __float2bfloat16(v.w - __bfloat162float(h3));
    hi[i] = make_uint2(pack_bf2(h0, h1), pack_bf2(h2, h3));
    lo[i] = make_uint2(pack_bf2(l0, l1), pack_bf2(l2, l3));
}

// ---------------- bf16 hi/lo GEMM via mma.sync (HMMA) -----------------------
// C[8192,1024] = A @ W^T + bias,  D = Ah*Wh + Ah*Wl + Al*Wh  (fp32 accum)
// CTA tile 128x128, BK=64 bf16, 3-stage cp.async pipeline, SW128 swizzle.
// 8 warps (2x4), warptile 64x32. mode 0: scatter to [B,H,S,dk]; mode 1: row-major.
#define G_STAGES 3
#define G_MAT_BYTES 16384              // 128 rows x 128B
#define G_STAGE_BYTES (4 * G_MAT_BYTES)
#define G_SMEM (G_STAGES * G_STAGE_BYTES)

__device__ __forceinline__ void stage_load(
    uint32_t sb, const __nv_bfloat16* __restrict__ Ah,
    const __nv_bfloat16* __restrict__ Al, const __nv_bfloat16* __restrict__ Wh,
    const __nv_bfloat16* __restrict__ Wl, int kt, int tid)
{
    const __nv_bfloat16* srcs[4] = {Ah, Al, Wh, Wl};
    #pragma unroll
    for (int m = 0; m < 4; ++m) {
        uint32_t mb = sb + m * G_MAT_BYTES;
        const __nv_bfloat16* sp = srcs[m];
        #pragma unroll
        for (int i = 0; i < 4; ++i) {
            int seg = tid + (i << 8);
            int row = seg >> 3, cs = seg & 7;
            const void* src = sp + (size_t)row * 1024 + (kt << 6) + (cs << 3);
            uint32_t dst = mb + row * 128 + ((cs << 4) ^ ((row & 7) << 4));
            cpa16(dst, src);
        }
    }
    CP_COMMIT();
}

__global__ __launch_bounds__(256, 1) void gemm_tc(
    const __nv_bfloat16* __restrict__ Ahi, const __nv_bfloat16* __restrict__ Alo,
    const __nv_bfloat16* __restrict__ Whi, const __nv_bfloat16* __restrict__ Wlo,
    const float* __restrict__ bias, float* __restrict__ out, int mode)
{
    extern __shared__ __align__(128) char dynsm[];
    __shared__ float bias_s[128];

    const int tid  = threadIdx.x;
    const int wid  = tid >> 5;
    const int lane = tid & 31;
    const int m0 = blockIdx.y << 7;
    const int n0 = blockIdx.x << 7;
    const int wm = (wid >> 2) << 6;     // 0 or 64
    const int wn = (wid & 3) << 5;      // 0,32,64,96

    if (tid < 128) bias_s[tid] = bias[n0 + tid];

    const uint32_t sb0 = smem_u32(dynsm);
    const __nv_bfloat16* pAh = Ahi + (size_t)m0 * 1024;
    const __nv_bfloat16* pAl = Alo + (size_t)m0 * 1024;
    const __nv_bfloat16* pWh = Whi + (size_t)n0 * 1024;
    const __nv_bfloat16* pWl = Wlo + (size_t)n0 * 1024;

    stage_load(sb0,                  pAh, pAl, pWh, pWl, 0, tid);
    stage_load(sb0 + G_STAGE_BYTES,  pAh, pAl, pWh, pWl, 1, tid);
    stage_load(sb0 + 2*G_STAGE_BYTES,pAh, pAl, pWh, pWl, 2, tid);

    float acc[4][4][4] = {};
    const int lr = lane & 15;           // ldmatrix row-within-16
    const int lxh = (lane >> 4) << 4;   // 0 or 16 (byte half offset)

    for (int j = 0; j < 16; ++j) {
        if (j < 14)      CP_WAIT(2);
        else if (j == 14) CP_WAIT(1);
        else              CP_WAIT(0);
        __syncthreads();

        const uint32_t sb = sb0 + (j % 3) * G_STAGE_BYTES;
        #pragma unroll
        for (int kk = 0; kk < 4; ++kk) {
            const int x = (kk << 5) + lxh;
            uint32_t ah[4][4], al[4][4];
            #pragma unroll
            for (int mi = 0; mi < 4; ++mi) {
                int row = wm + (mi << 4) + lr;
                uint32_t ad = sb + row * 128 + (x ^ ((row & 7) << 4));
                LDSM4(ah[mi][0], ah[mi][1], ah[mi][2], ah[mi][3], ad);
                LDSM4(al[mi][0], al[mi][1], al[mi][2], al[mi][3],
                      ad + G_MAT_BYTES);
            }
            uint32_t whf[4][2], wlf[4][2];
            #pragma unroll
            for (int g = 0; g < 2; ++g) {
                int row = wn + (g << 4) + lr;
                uint32_t wd = sb + 2 * G_MAT_BYTES + row * 128 +
                              (x ^ ((row & 7) << 4));
                uint32_t r0, r1, r2, r3;
                LDSM4(r0, r1, r2, r3, wd);
                whf[g*2][0] = r0; whf[g*2][1] = r2;
                whf[g*2+1][0] = r1; whf[g*2+1][1] = r3;
                LDSM4(r0, r1, r2, r3, wd + G_MAT_BYTES);
                wlf[g*2][0] = r0; wlf[g*2][1] = r2;
                wlf[g*2+1][0] = r1; wlf[g*2+1][1] = r3;
            }
            #pragma unroll
            for (int mi = 0; mi < 4; ++mi)
                #pragma unroll
                for (int ni = 0; ni < 4; ++ni) {
                    MMA16816(acc[mi][ni], ah[mi], whf[ni]);
                    MMA16816(acc[mi][ni], ah[mi], wlf[ni]);
                    MMA16816(acc[mi][ni], al[mi], whf[ni]);
                }
        }
        __syncthreads();
        if (j + 3 < 16)
            stage_load(sb0 + (j % 3) * G_STAGE_BYTES, pAh, pAl, pWh, pWl,
                       j + 3, tid);
    }

    // ---------------- epilogue ----------------
    const int rbase = m0 + wm + (lane >> 2);
    const int cbase = n0 + wn + ((lane & 3) << 1);
    #pragma unroll
    for (int mi = 0; mi < 4; ++mi) {
        #pragma unroll
        for (int ni = 0; ni < 4; ++ni) {
            int col = cbase + (ni << 3);
            float b0 = bias_s[col - n0], b1 = bias_s[col - n0 + 1];
            #pragma unroll
            for (int half = 0; half < 2; ++half) {
                int row = rbase + (mi << 4) + (half << 3);
                float2 v = make_float2(acc[mi][ni][half*2]   + b0,
                                       acc[mi][ni][half*2+1] + b1);
                if (mode == 0) {
                    int h = col >> 6, d = col & 63;
                    int b = row >> 11, s = row & 2047;
                    *reinterpret_cast<float2*>(
                        &out[((size_t)((b << 4) + h) * 2048 + s) * 64 + d]) = v;
                } else {
                    *reinterpret_cast<float2*>(
                        &out[(size_t)row * 1024 + col]) = v;
                }
            }
        }
    }
}

// ---------------- flash attention (fp32, unchanged from R1) -----------------
__global__ __launch_bounds__(256) void attn_kernel(const int* __restrict__ mask)
{
    extern __shared__ float sm[];
    float* Qts = sm;
    float* Kts = Qts + 64 * 68;
    float* Vsm = Kts + 64 * 68;
    float* Psm = Vsm + 64 * 68;
    int*   Msm = reinterpret_cast<int*>(Psm + 64 * 68);

    const int tid = threadIdx.x;
    const int tx = tid & 15, ty = tid >> 4;
    const int bh = blockIdx.y;
    const int b = bh >> 4, h = bh & 15;
    const int q0 = blockIdx.x << 6;

    const float* Qg = g_q + (size_t)bh * 2048 * 64;
    const float* Kg = g_k + (size_t)bh * 2048 * 64;
    const float* Vg = g_v + (size_t)bh * 2048 * 64;
    const int*   Mg = mask + (size_t)b * 2048 * 2048;

    #pragma unroll
    for (int i = 0; i < 4; ++i) {
        int idx = tid + (i << 8);
        int r = idx >> 4, c = (idx & 15) << 2;
        float4 qv = *reinterpret_cast<const float4*>(Qg + (size_t)(q0 + r) * 64 + c);
        Qts[(c+0)*68 + r] = qv.x;
        Qts[(c+1)*68 + r] = qv.y;
        Qts[(c+2)*68 + r] = qv.z;
        Qts[(c+3)*68 + r] = qv.w;
    }

    float o[4][4] = {};
    float mrow[4] = {-1e30f, -1e30f, -1e30f, -1e30f};
    float lrow[4] = {};

    for (int k0 = 0; k0 < 2048; k0 += 64) {
        __syncthreads();
        #pragma unroll
        for (int i = 0; i < 4; ++i) {
            int idx = tid + (i << 8);
            int r = idx >> 4, c = (idx & 15) << 2;
            float4 kv = *reinterpret_cast<const float4*>(Kg + (size_t)(k0 + r) * 64 + c);
            Kts[(c+0)*68 + r] = kv.x;
            Kts[(c+1)*68 + r] = kv.y;
            Kts[(c+2)*68 + r] = kv.z;
            Kts[(c+3)*68 + r] = kv.w;
            float4 vv = *reinterpret_cast<const float4*>(Vg + (size_t)(k0 + r) * 64 + c);
            *reinterpret_cast<float4*>(&Vsm[r*68 + c]) = vv;
            int4 mv = *reinterpret_cast<const int4*>(Mg + (size_t)(q0 + r) * 2048 + k0 + c);
            *reinterpret_cast<int4*>(&Msm[r*68 + c]) = mv;
        }
        __syncthreads();

        float sc[4][4] = {};
        #pragma unroll 8
        for (int d = 0; d < 64; ++d) {
            float4 q4 = *reinterpret_cast<const float4*>(&Qts[d*68 + (ty << 2)]);
            float4 k4 = *reinterpret_cast<const float4*>(&Kts[d*68 + (tx << 2)]);
            float qa[4] = {q4.x, q4.y, q4.z, q4.w};
            float ka[4] = {k4.x, k4.y, k4.z, k4.w};
            #pragma unroll
            for (int i = 0; i < 4; ++i)
                #pragma unroll
                for (int j = 0; j < 4; ++j)
                    sc[i][j] = fmaf(qa[i], ka[j], sc[i][j]);
        }

        #pragma unroll
        for (int i = 0; i < 4; ++i) {
            const int qr = (ty << 2) + i;
            float p[4];
            #pragma unroll
            for (int j = 0; j < 4; ++j) {
                int mk = Msm[qr*68 + (tx << 2) + j];
                p[j] = (mk == 0) ? EPS_VAL : sc[i][j] * 0.125f;
            }
            float tm = fmaxf(fmaxf(p[0], p[1]), fmaxf(p[2], p[3]));
            #pragma unroll
            for (int off = 8; off > 0; off >>= 1)
                tm = fmaxf(tm, __shfl_xor_sync(0xffffffffu, tm, off));
            float mn = fmaxf(mrow[i], tm);
            float corr = __expf(mrow[i] - mn);
            float rs = 0.f;
            #pragma unroll
            for (int j = 0; j < 4; ++j) {
                float e = __expf(p[j] - mn);
                Psm[qr*68 + (tx << 2) + j] = e;
                rs += e;
            }
            #pragma unroll
            for (int off = 8; off > 0; off >>= 1)
                rs += __shfl_xor_sync(0xffffffffu, rs, off);
            lrow[i] = lrow[i] * corr + rs;
            mrow[i] = mn;
            #pragma unroll
            for (int j = 0; j < 4; ++j) o[i][j] *= corr;
        }
        __syncthreads();

        #pragma unroll 4
        for (int k = 0; k < 64; k += 4) {
            float4 pv[4], vv[4];
            #pragma unroll
            for (int i = 0; i < 4; ++i)
                pv[i] = *reinterpret_cast<const float4*>(&Psm[((ty << 2) + i)*68 + k]);
            #pragma unroll
            for (int e = 0; e < 4; ++e)
                vv[e] = *reinterpret_cast<const float4*>(&Vsm[(k + e)*68 + (tx << 2)]);
            #pragma unroll
            for (int i = 0; i < 4; ++i) {
                float pa[4] = {pv[i].x, pv[i].y, pv[i].z, pv[i].w};
                #pragma unroll
                for (int e = 0; e < 4; ++e) {
                    o[i][0] = fmaf(pa[e], vv[e].x, o[i][0]);
                    o[i][1] = fmaf(pa[e], vv[e].y, o[i][1]);
                    o[i][2] = fmaf(pa[e], vv[e].z, o[i][2]);
                    o[i][3] = fmaf(pa[e], vv[e].w, o[i][3]);
                }
            }
        }
    }

    #pragma unroll
    for (int i = 0; i < 4; ++i) {
        float inv = 1.f / lrow[i];
        int q = q0 + (ty << 2) + i;
        float4 r = make_float4(o[i][0]*inv, o[i][1]*inv, o[i][2]*inv, o[i][3]*inv);
        *reinterpret_cast<float4*>(
            &g_ao[((size_t)(b * 2048 + q)) * 1024 + h * 64 + (tx << 2)]) = r;
    }
}

// ---------------------------------------------------------------------------
extern "C" void kernel_launch(void* const* d_in, const int* in_sizes, int n_in,
                              void* d_out, int out_size)
{
    const float* query = (const float*)d_in[0];
    const float* key_  = (const float*)d_in[1];
    const float* value = (const float*)d_in[2];
    const int*   mask  = (const int*)  d_in[3];
    const float* wq = (const float*)d_in[4];
    const float* bq = (const float*)d_in[5];
    const float* wk = (const float*)d_in[6];
    const float* bk = (const float*)d_in[7];
    const float* wv = (const float*)d_in[8];
    const float* bv = (const float*)d_in[9];
    const float* wo = (const float*)d_in[10];
    const float* bo = (const float*)d_in[11];

    float *pq, *pk, *pv, *pao;
    __nv_bfloat16 *pahi, *palo, *pwhi, *pwlo;
    cudaGetSymbolAddress((void**)&pq,   g_q);
    cudaGetSymbolAddress((void**)&pk,   g_k);
    cudaGetSymbolAddress((void**)&pv,   g_v);
    cudaGetSymbolAddress((void**)&pao,  g_ao);
    cudaGetSymbolAddress((void**)&pahi, g_ahi);
    cudaGetSymbolAddress((void**)&palo, g_alo);
    cudaGetSymbolAddress((void**)&pwhi, g_whi);
    cudaGetSymbolAddress((void**)&pwlo, g_wlo);

    cudaFuncSetAttribute(gemm_tc,
                         cudaFuncAttributeMaxDynamicSharedMemorySize, G_SMEM);
    const int attn_smem = 5 * 64 * 68 * 4;
    cudaFuncSetAttribute(attn_kernel,
                         cudaFuncAttributeMaxDynamicSharedMemorySize, attn_smem);

    #define PROJ(Asrc, Wsrc, Bsrc, Odst, MODE)                                \
        conv_split<<<8192, 256>>>((const float4*)(Asrc), (uint2*)pahi,        \
                                  (uint2*)palo, 2097152);                     \
        conv_split<<<1024, 256>>>((const float4*)(Wsrc), (uint2*)pwhi,        \
                                  (uint2*)pwlo, 262144);                      \
        gemm_tc<<<dim3(8, 64), 256, G_SMEM>>>(pahi, palo, pwhi, pwlo,         \
                                              (Bsrc), (Odst), (MODE));

    PROJ(query, wq, bq, pq, 0)
    PROJ(key_,  wk, bk, pk, 0)
    PROJ(value, wv, bv, pv, 0)

    attn_kernel<<<dim3(32, 64), 256, attn_smem>>>(mask);

    PROJ(pao, wo, bo, (float*)d_out, 1)
    #undef PROJ
}